// round 3
// baseline (speedup 1.0000x reference)
#include <cuda_runtime.h>

// Fused JPEG decode: dequant + separable 8x8 IDCT (Y, Cb, Cr) + 2x nearest
// chroma upsample + YCbCr->RGB + clip + /255, one kernel, no intermediates.
//
// CTA = 256 threads = 4 groups x 64 threads. Each group handles a 16x16 pixel
// sub-tile (4 Y blocks, 1 Cb, 1 Cr). CTA covers 16 rows x 64 cols of output.
// Grid = out_size / (3*16*64) tiles; per-tile geometry derived in-kernel from
// the image_height / image_width device scalars.

__global__ __launch_bounds__(256) void jpeg_decode_kernel(
    const float* __restrict__ yc,  const float* __restrict__ cbc_in,
    const float* __restrict__ crc_in,
    const float* __restrict__ ytab, const float* __restrict__ ctab,
    const float* __restrict__ alpha,
    const float* __restrict__ shiftp, const float* __restrict__ matp,
    const int* __restrict__ Hp, const int* __restrict__ Wp,
    const int* __restrict__ facp,
    float* __restrict__ out)
{
    __shared__ float sCm[64];                // basis: Cm[f*8+p] = cos((2p+1) f pi/16)
    __shared__ float sDqY[64], sDqC[64];     // table*alpha*factor*0.25
    __shared__ float sA[4][64], sT[4][64];   // per-group IDCT scratch
    __shared__ float sCb[4][64], sCr[4][64]; // decoded chroma (shift applied)
    __shared__ float sMat[9], sShift[3];
    __shared__ __align__(16) float sOut[3 * 16 * 64];  // staged RGB tile

    const int tid = threadIdx.x;
    const int H = *Hp, W = *Wp;

    if (tid < 64) {
        int f = tid >> 3, p = tid & 7;
        sCm[tid] = cospif((float)((2 * p + 1) * f) / 16.0f);
        float fac = (float)(*facp) * 0.25f;
        sDqY[tid] = ytab[tid] * alpha[tid] * fac;
        sDqC[tid] = ctab[tid] * alpha[tid] * fac;
    } else if (tid < 73) {
        sMat[tid - 64] = matp[tid - 64];
    } else if (tid < 76) {
        sShift[tid - 73] = shiftp[tid - 73];
    }

    const int g = tid >> 6;        // group 0..3
    const int t = tid & 63;        // lane within group
    const int u = t >> 3, v = t & 7;

    // Tile decomposition: CTA covers rows [h0, h0+16), cols [w0, w0+64).
    const int tilesW = W >> 6;
    const int tilesH = H >> 4;
    int tau = blockIdx.x;
    const int tc = tau % tilesW; tau /= tilesW;
    const int tr = tau % tilesH;
    const int b  = tau / tilesH;
    const int w0 = tc << 6;
    const int h0 = tr << 4;

    // ---- Prefetch all 6 coefficient values (one latency, MLP=6) ----
    const int cbcol = (tc << 2) + g;       // chroma block col for this group
    const int nbw2  = W >> 4;              // chroma blocks per row
    const long long cBase =
        ((long long)(b * (H >> 4) + tr) * nbw2 + cbcol) * 64 + t;
    float coefCb = cbc_in[cBase];
    float coefCr = crc_in[cBase];

    const int nbw1 = W >> 3;               // luma blocks per row
    float coefY[4];
    #pragma unroll
    for (int q = 0; q < 4; ++q) {
        int qr = q >> 1, qc = q & 1;
        int br = (tr << 1) + qr;
        int bc = (cbcol << 1) + qc;
        long long yBase =
            ((long long)(b * (H >> 3) + br) * nbw1 + bc) * 64 + t;
        coefY[q] = yc[yBase];
    }

    __syncthreads();   // init tables ready

    // Separable 8x8 IDCT on this group's staged block.
    auto idct8 = [&](float coeff, const float* __restrict__ dq) -> float {
        sA[g][t] = coeff * dq[t];
        __syncthreads();
        float acc = 0.f;
        #pragma unroll
        for (int k = 0; k < 8; ++k)
            acc = fmaf(sA[g][(u << 3) + k], sCm[(k << 3) + v], acc);
        sT[g][t] = acc;
        __syncthreads();
        float r = 0.f;
        #pragma unroll
        for (int k = 0; k < 8; ++k)
            r = fmaf(sCm[(k << 3) + u], sT[g][(k << 3) + v], r);
        __syncthreads();
        return r;
    };

    // Chroma first (results needed cross-thread for upsample).
    sCb[g][t] = idct8(coefCb, sDqC) + 128.0f + sShift[1];
    sCr[g][t] = idct8(coefCr, sDqC) + 128.0f + sShift[2];

    float yv[4];
    #pragma unroll
    for (int q = 0; q < 4; ++q)
        yv[q] = idct8(coefY[q], sDqY) + 128.0f + sShift[0];
    // (trailing __syncthreads inside idct8 makes sCb/sCr visible here)

    const float m0 = sMat[0], m1 = sMat[1], m2 = sMat[2];
    const float m3 = sMat[3], m4 = sMat[4], m5 = sMat[5];
    const float m6 = sMat[6], m7 = sMat[7], m8 = sMat[8];
    const float inv255 = 1.0f / 255.0f;

    #pragma unroll
    for (int q = 0; q < 4; ++q) {
        int qr = q >> 1, qc = q & 1;
        int pr = (qr << 3) + u;            // row within 16x16 sub-tile
        int pc = (qc << 3) + v;            // col within 16x16 sub-tile
        int ci = ((pr >> 1) << 3) + (pc >> 1);
        float Y_  = yv[q];
        float Cb_ = sCb[g][ci];
        float Cr_ = sCr[g][ci];
        float R  = fmaf(Cr_, m6, fmaf(Cb_, m3, Y_ * m0));
        float G  = fmaf(Cr_, m7, fmaf(Cb_, m4, Y_ * m1));
        float Bv = fmaf(Cr_, m8, fmaf(Cb_, m5, Y_ * m2));
        int col = (g << 4) + pc;
        sOut[(0 * 16 + pr) * 64 + col] = fminf(fmaxf(R,  0.f), 255.f) * inv255;
        sOut[(1 * 16 + pr) * 64 + col] = fminf(fmaxf(G,  0.f), 255.f) * inv255;
        sOut[(2 * 16 + pr) * 64 + col] = fminf(fmaxf(Bv, 0.f), 255.f) * inv255;
    }
    __syncthreads();

    // Coalesced float4 writes: 768 float4s, 3 per thread; each warp emits
    // 512B contiguous per iteration.
    float4* out4 = reinterpret_cast<float4*>(out);
    #pragma unroll
    for (int i = tid; i < 768; i += 256) {
        int c    = i >> 8;          // channel
        int rem  = i & 255;
        int r    = rem >> 4;        // row 0..15
        int qcol = rem & 15;        // float4 col 0..15
        long long off =
            (((long long)b * 3 + c) * H + (h0 + r)) * W + w0 + (qcol << 2);
        out4[off >> 2] =
            *reinterpret_cast<float4*>(&sOut[(c * 16 + r) * 64 + (qcol << 2)]);
    }
}

extern "C" void kernel_launch(void* const* d_in, const int* in_sizes, int n_in,
                              void* d_out, int out_size) {
    // d_in order (metadata): y, cb, cr, y_table, c_table, alpha, dct_tensor,
    //                        shift, matrix, image_height, image_width, factor
    const float* yc   = (const float*)d_in[0];
    const float* cbv  = (const float*)d_in[1];
    const float* crv  = (const float*)d_in[2];
    const float* ytab = (const float*)d_in[3];
    const float* ctab = (const float*)d_in[4];
    const float* alp  = (const float*)d_in[5];
    // d_in[6] = dct_tensor (unused; basis built analytically with cospif)
    const float* shf  = (const float*)d_in[7];
    const float* mat  = (const float*)d_in[8];
    const int*   Hp   = (const int*)d_in[9];
    const int*   Wp   = (const int*)d_in[10];
    const int*   fac  = (const int*)d_in[11];
    float* out = (float*)d_out;

    // One CTA per 16x64x3-float output tile.
    int tiles = out_size / (3 * 16 * 64);
    jpeg_decode_kernel<<<tiles, 256>>>(yc, cbv, crv, ytab, ctab, alp,
                                       shf, mat, Hp, Wp, fac, out);
}

// round 8
// speedup vs baseline: 1.5198x; 1.5198x over previous
#include <cuda_runtime.h>

// Fused JPEG decode: dequant + separable 8x8 IDCT (Y, Cb, Cr) + 2x nearest
// chroma upsample + YCbCr->RGB + clip + /255. Single kernel.
//
// CTA = 256 threads = 8 warps. CTA covers a 16-row x 64-col output tile.
// Each WARP owns 3 whole 8x8 blocks (2 Y blocks in its 8-col strip + 1 chroma
// block), 2 pixels per lane. IDCT passes are warp-private: pass-1 reads rows
// via LDS.128, writes the intermediate TRANSPOSED (row pitch 12 -> bank
// conflict free), pass-2 reads rows of the transpose via LDS.128. Basis for
// pass 1 lives in registers; pass-2 basis rows are LDS.128 temporaries.
// Only 3 CTA-wide barriers; everything else is __syncwarp.

__device__ __forceinline__ float dot8r(float4 a, float4 b, const float* c) {
    float s = a.x * c[0];
    s = fmaf(a.y, c[1], s); s = fmaf(a.z, c[2], s); s = fmaf(a.w, c[3], s);
    s = fmaf(b.x, c[4], s); s = fmaf(b.y, c[5], s); s = fmaf(b.z, c[6], s);
    s = fmaf(b.w, c[7], s);
    return s;
}
__device__ __forceinline__ float dot8v(float4 a, float4 b, float4 c, float4 d) {
    float s = a.x * c.x;
    s = fmaf(a.y, c.y, s); s = fmaf(a.z, c.z, s); s = fmaf(a.w, c.w, s);
    s = fmaf(b.x, d.x, s); s = fmaf(b.y, d.y, s); s = fmaf(b.z, d.z, s);
    s = fmaf(b.w, d.w, s);
    return s;
}

__global__ __launch_bounds__(256) void jpeg_decode_kernel(
    const float* __restrict__ yc,  const float* __restrict__ cbc_in,
    const float* __restrict__ crc_in,
    const float* __restrict__ ytab, const float* __restrict__ ctab,
    const float* __restrict__ alpha,
    const float* __restrict__ shiftp, const float* __restrict__ matp,
    const int* __restrict__ Hp, const int* __restrict__ Wp,
    const int* __restrict__ facp,
    float* __restrict__ out)
{
    __shared__ __align__(16) float ccT[64];       // ccT[p*8+f] = cos((2p+1) f pi/16)
    __shared__ float sDqY[64], sDqC[64];          // table*alpha*factor*0.25
    __shared__ float sMat[9], sShift[3];
    __shared__ __align__(16) float sA[8][64];     // per-warp coeff block
    __shared__ __align__(16) float sT[8][96];     // per-warp transposed pass-1 (pitch 12)
    __shared__ float sCb[4][64], sCr[4][64];      // decoded chroma (+128+shift)
    __shared__ __align__(16) float sOut[3 * 16 * 68];  // RGB stage, pitch 68 (no conflicts)

    const int tid = threadIdx.x;
    const int H = *Hp, W = *Wp;

    if (tid < 64) {
        int p = tid >> 3, f = tid & 7;
        ccT[tid] = cospif((float)((2 * p + 1) * f) / 16.0f);
        float fac = (float)(*facp) * 0.25f;
        sDqY[tid] = ytab[tid] * alpha[tid] * fac;
        sDqC[tid] = ctab[tid] * alpha[tid] * fac;
    } else if (tid < 73) {
        sMat[tid - 64] = matp[tid - 64];
    } else if (tid < 76) {
        sShift[tid - 73] = shiftp[tid - 73];
    }

    const int w = tid >> 5, l = tid & 31;   // warp id, lane
    const int i = l >> 3, j = l & 7;        // lane -> (row 0..3, col 0..7); also owns row i+4
    const int p0 = (i << 3) + j, p1 = p0 + 32;

    // Tile decomposition: CTA covers rows [h0,h0+16), cols [w0,w0+64).
    const int tilesW = W >> 6, tilesH = H >> 4;
    int tau = blockIdx.x;
    const int tc = tau % tilesW; tau /= tilesW;
    const int tr = tau % tilesH;
    const int b  = tau / tilesH;
    const int w0 = tc << 6, h0 = tr << 4;

    // ---- Prefetch all 6 coefficients up front (MLP=6) ----
    const int s = w & 3;                              // chroma subtile for this warp
    const float* cptr = (w < 4) ? cbc_in : crc_in;
    const long long cBase =
        (((long long)(b * (H >> 4) + tr)) * (W >> 4) + (tc << 2) + s) << 6;
    float cf0 = cptr[cBase + p0], cf1 = cptr[cBase + p1];

    const long long yB0 =
        (((long long)(b * (H >> 3) + (tr << 1))) * (W >> 3) + (tc << 3) + w) << 6;
    const long long yB1 =
        (((long long)(b * (H >> 3) + (tr << 1) + 1)) * (W >> 3) + (tc << 3) + w) << 6;
    float yf00 = yc[yB0 + p0], yf01 = yc[yB0 + p1];
    float yf10 = yc[yB1 + p0], yf11 = yc[yB1 + p1];

    __syncthreads();   // tables ready                                   [BAR 1]

    // Pass-1 basis column (fixed per lane) in registers.
    float cv[8];
    {
        float4 v0 = *reinterpret_cast<const float4*>(&ccT[j << 3]);
        float4 v1 = *reinterpret_cast<const float4*>(&ccT[(j << 3) + 4]);
        cv[0] = v0.x; cv[1] = v0.y; cv[2] = v0.z; cv[3] = v0.w;
        cv[4] = v1.x; cv[5] = v1.y; cv[6] = v1.z; cv[7] = v1.w;
    }
    const float dqy0 = sDqY[p0], dqy1 = sDqY[p1];
    const float dqc0 = sDqC[p0], dqc1 = sDqC[p1];

    float* A = sA[w];
    float* T = sT[w];
    const float4* C4 = reinterpret_cast<const float4*>(ccT);

    // Warp-private 8x8 IDCT; lane produces outputs at rows i and i+4, col j.
    auto idct2 = [&](float a0c, float a1c, float& o0, float& o1) {
        A[p0] = a0c; A[p1] = a1c;
        __syncwarp();
        const float4* Ar = reinterpret_cast<const float4*>(A);
        float t0 = dot8r(Ar[i << 1],       Ar[(i << 1) + 1],       cv);
        float t1 = dot8r(Ar[(i + 4) << 1], Ar[((i + 4) << 1) + 1], cv);
        T[j * 12 + i]     = t0;        // transposed store, pitch 12: conflict-free
        T[j * 12 + i + 4] = t1;
        __syncwarp();
        float4 tv0 = *reinterpret_cast<const float4*>(&T[j * 12]);
        float4 tv1 = *reinterpret_cast<const float4*>(&T[j * 12 + 4]);
        o0 = dot8v(tv0, tv1, C4[i << 1],       C4[(i << 1) + 1]);
        o1 = dot8v(tv0, tv1, C4[(i + 4) << 1], C4[((i + 4) << 1) + 1]);
        __syncwarp();                  // protect A/T reuse
    };

    // Chroma block first (cross-warp consumers).
    {
        float r0, r1;
        idct2(cf0 * dqc0, cf1 * dqc1, r0, r1);
        float* sC  = (w < 4) ? sCb[s] : sCr[s];
        float  shC = (w < 4) ? sShift[1] : sShift[2];
        sC[p0] = r0 + 128.0f + shC;
        sC[p1] = r1 + 128.0f + shC;
    }

    float yv[4];
    idct2(yf00 * dqy0, yf01 * dqy1, yv[0], yv[1]);   // Y block row 0, col-strip w
    idct2(yf10 * dqy0, yf11 * dqy1, yv[2], yv[3]);   // Y block row 1

    __syncthreads();   // chroma visible to all warps                    [BAR 2]

    const float m0 = sMat[0], m1 = sMat[1], m2 = sMat[2];
    const float m3 = sMat[3], m4 = sMat[4], m5 = sMat[5];
    const float m6 = sMat[6], m7 = sMat[7], m8 = sMat[8];
    const float sh0 = sShift[0];
    const float inv255 = 1.0f / 255.0f;

    const int g2  = w >> 1;                    // 16x16 subtile of this warp
    const int pcl = ((w & 1) << 3) + j;        // col within subtile (0..15)
    const int pca = (w << 3) + j;              // absolute col within tile (0..63)

    #pragma unroll
    for (int q = 0; q < 4; ++q) {
        int qr = q >> 1, h = q & 1;
        int pr = (qr << 3) + i + (h << 2);     // row within 16
        float Y_ = yv[(qr << 1) + h] + 128.0f + sh0;
        int ci = ((pr >> 1) << 3) + (pcl >> 1);
        float Cb_ = sCb[g2][ci];
        float Cr_ = sCr[g2][ci];
        float R  = fmaf(Cr_, m6, fmaf(Cb_, m3, Y_ * m0));
        float G  = fmaf(Cr_, m7, fmaf(Cb_, m4, Y_ * m1));
        float Bv = fmaf(Cr_, m8, fmaf(Cb_, m5, Y_ * m2));
        sOut[(0 * 16 + pr) * 68 + pca] = fminf(fmaxf(R,  0.f), 255.f) * inv255;
        sOut[(1 * 16 + pr) * 68 + pca] = fminf(fmaxf(G,  0.f), 255.f) * inv255;
        sOut[(2 * 16 + pr) * 68 + pca] = fminf(fmaxf(Bv, 0.f), 255.f) * inv255;
    }
    __syncthreads();                                               //    [BAR 3]

    // Coalesced float4 stores: 768 float4s, 3 per thread, 512B/warp/iter.
    float4* out4 = reinterpret_cast<float4*>(out);
    #pragma unroll
    for (int it = tid; it < 768; it += 256) {
        int c    = it >> 8;
        int rem  = it & 255;
        int r    = rem >> 4;
        int qcol = rem & 15;
        long long off =
            (((long long)b * 3 + c) * H + (h0 + r)) * W + w0 + (qcol << 2);
        out4[off >> 2] =
            *reinterpret_cast<const float4*>(&sOut[(c * 16 + r) * 68 + (qcol << 2)]);
    }
}

extern "C" void kernel_launch(void* const* d_in, const int* in_sizes, int n_in,
                              void* d_out, int out_size) {
    // metadata order: y, cb, cr, y_table, c_table, alpha, dct_tensor,
    //                 shift, matrix, image_height, image_width, factor
    const float* yc   = (const float*)d_in[0];
    const float* cbv  = (const float*)d_in[1];
    const float* crv  = (const float*)d_in[2];
    const float* ytab = (const float*)d_in[3];
    const float* ctab = (const float*)d_in[4];
    const float* alp  = (const float*)d_in[5];
    // d_in[6] dct_tensor unused (basis built analytically with cospif)
    const float* shf  = (const float*)d_in[7];
    const float* mat  = (const float*)d_in[8];
    const int*   Hp   = (const int*)d_in[9];
    const int*   Wp   = (const int*)d_in[10];
    const int*   fac  = (const int*)d_in[11];
    float* out = (float*)d_out;

    int tiles = out_size / (3 * 16 * 64);   // one CTA per 16x64 output tile
    jpeg_decode_kernel<<<tiles, 256>>>(yc, cbv, crv, ytab, ctab, alp,
                                       shf, mat, Hp, Wp, fac, out);
}

// round 9
// speedup vs baseline: 1.5726x; 1.0347x over previous
#include <cuda_runtime.h>

// Fused JPEG decode: dequant + 8x8 IDCT (Y, Cb, Cr) + 2x nearest chroma
// upsample + YCbCr->RGB + clip + /255. Single kernel.
//
// CTA = 256 threads = 8 warps, covering a 16-row x 64-col output tile.
// Each warp owns 3 whole 8x8 blocks (2 Y in its 8-col strip + 1 chroma).
// The separable IDCT runs ENTIRELY in registers via warp shuffles:
//   pass 1: gather the coefficient column across lanes (6 SHFL.XOR) and
//           compute T[i][j], T[i+4][j] with a per-lane register basis;
//   pass 2: exchange with the j^4 partner first (2 SHFL + row select),
//           then gather the selected row (masks 1,2 -> 6 SHFL) and compute
//           two horizontally adjacent output pixels (row r, cols v0,v0+1).
// Outputs go straight to gmem as STG.64 (full 32B sectors) -- no smem
// staging tile. Only chroma transits smem (cross-warp upsample).
// 2 CTA-wide barriers total.

__global__ __launch_bounds__(256) void jpeg_decode_kernel(
    const float* __restrict__ yc,  const float* __restrict__ cbc_in,
    const float* __restrict__ crc_in,
    const float* __restrict__ ytab, const float* __restrict__ ctab,
    const float* __restrict__ alpha,
    const float* __restrict__ shiftp, const float* __restrict__ matp,
    const int* __restrict__ Hp, const int* __restrict__ Wp,
    const int* __restrict__ facp,
    float* __restrict__ out)
{
    __shared__ float cF[64];                 // cF[x*8+u] = cos((2u+1) x pi/16)
    __shared__ float sDqY[64], sDqC[64];     // table*alpha*factor*0.25
    __shared__ float sMat[9], sShift[3];
    __shared__ float sCb[4][64], sCr[4][64]; // decoded chroma (+128+shift)

    const int tid = threadIdx.x;
    const int H = *Hp, W = *Wp;

    if (tid < 64) {
        int x = tid >> 3, u = tid & 7;
        cF[tid] = cospif((float)((2 * u + 1) * x) / 16.0f);
        float fac = (float)(*facp) * 0.25f;
        sDqY[tid] = ytab[tid] * alpha[tid] * fac;
        sDqC[tid] = ctab[tid] * alpha[tid] * fac;
    } else if (tid < 73) {
        sMat[tid - 64] = matp[tid - 64];
    } else if (tid < 76) {
        sShift[tid - 73] = shiftp[tid - 73];
    }

    const int w = tid >> 5, l = tid & 31;    // warp, lane
    const int i = l >> 3, j = l & 7;         // coeff ownership: (i,j),(i+4,j)
    const int p0 = (i << 3) + j, p1 = p0 + 32;
    const int v0 = (j & 3) << 1;             // output col pair base (0,2,4,6)
    const bool hi = (j >= 4);
    const int rr = i + (hi ? 4 : 0);         // output row within block

    // Tile decomposition: CTA covers rows [h0,h0+16), cols [w0,w0+64).
    const int tilesW = W >> 6, tilesH = H >> 4;
    int tau = blockIdx.x;
    const int tc = tau % tilesW; tau /= tilesW;
    const int tr = tau % tilesH;
    const int b  = tau / tilesH;
    const int w0 = tc << 6, h0 = tr << 4;

    // ---- Prefetch all 6 coefficients up front (MLP=6) ----
    const int s = w & 3;                     // chroma subtile of this warp
    const float* cptr = (w < 4) ? cbc_in : crc_in;
    const long long cBase =
        (((long long)(b * (H >> 4) + tr)) * (W >> 4) + (tc << 2) + s) << 6;
    float cf0 = cptr[cBase + p0], cf1 = cptr[cBase + p1];

    const long long yB0 =
        (((long long)(b * (H >> 3) + (tr << 1))) * (W >> 3) + (tc << 3) + w) << 6;
    const long long yB1 =
        (((long long)(b * (H >> 3) + (tr << 1) + 1)) * (W >> 3) + (tc << 3) + w) << 6;
    float yf00 = yc[yB0 + p0], yf01 = yc[yB0 + p1];
    float yf10 = yc[yB1 + p0], yf11 = yc[yB1 + p1];

    __syncthreads();   // tables ready                                   [BAR 1]

    // ---- Per-lane register basis (loaded once; broadcast-friendly) ----
    // Pass-1 gather register k holds X[a_k][j] with a_k = (i^(k>>1)) + 4*(k&1).
    // Pass-2 gather register k holds T[rr][j^e_k] with e_k = ((k&1)<<2)|(k>>1).
    float B0[8], B1[8], P0[8], P1[8];
    #pragma unroll
    for (int k = 0; k < 8; ++k) {
        int e = ((k & 1) << 2) | (k >> 1);
        int a = (i ^ (k >> 1)) + ((k & 1) << 2);
        B0[k] = cF[(a << 3) + i];
        B1[k] = cF[(a << 3) + i + 4];
        int y = j ^ e;
        P0[k] = cF[(y << 3) + v0];
        P1[k] = cF[(y << 3) + v0 + 1];
    }
    const float dqy0 = sDqY[p0], dqy1 = sDqY[p1];
    const float dqc0 = sDqC[p0], dqc1 = sDqC[p1];

    // Register-only 8x8 IDCT; lane emits out[rr][v0], out[rr][v0+1].
    auto idct_sh = [&](float a0, float a1, float& o0, float& o1) {
        // pass-1 gather: column j of the block (masks 8, 16)
        float X0 = a0, X1 = a1;
        float X2 = __shfl_xor_sync(0xffffffffu, X0, 8);
        float X3 = __shfl_xor_sync(0xffffffffu, X1, 8);
        float X4 = __shfl_xor_sync(0xffffffffu, X0, 16);
        float X5 = __shfl_xor_sync(0xffffffffu, X1, 16);
        float X6 = __shfl_xor_sync(0xffffffffu, X2, 16);
        float X7 = __shfl_xor_sync(0xffffffffu, X3, 16);
        float t0 = X0 * B0[0], t1 = X0 * B1[0];
        t0 = fmaf(X1, B0[1], t0); t1 = fmaf(X1, B1[1], t1);
        t0 = fmaf(X2, B0[2], t0); t1 = fmaf(X2, B1[2], t1);
        t0 = fmaf(X3, B0[3], t0); t1 = fmaf(X3, B1[3], t1);
        t0 = fmaf(X4, B0[4], t0); t1 = fmaf(X4, B1[4], t1);
        t0 = fmaf(X5, B0[5], t0); t1 = fmaf(X5, B1[5], t1);
        t0 = fmaf(X6, B0[6], t0); t1 = fmaf(X6, B1[6], t1);
        t0 = fmaf(X7, B0[7], t0); t1 = fmaf(X7, B1[7], t1);
        // t0 = T[i][j], t1 = T[i+4][j]
        // pass-2: exchange with j^4 partner, select row rr, gather masks 1,2
        float s0 = __shfl_xor_sync(0xffffffffu, t0, 4);  // T[i][j^4]
        float s1 = __shfl_xor_sync(0xffffffffu, t1, 4);  // T[i+4][j^4]
        float T0 = hi ? t1 : t0;   // T[rr][j]
        float T1 = hi ? s1 : s0;   // T[rr][j^4]
        float T2 = __shfl_xor_sync(0xffffffffu, T0, 1);  // T[rr][j^1]
        float T3 = __shfl_xor_sync(0xffffffffu, T1, 1);  // T[rr][j^5]
        float T4 = __shfl_xor_sync(0xffffffffu, T0, 2);  // T[rr][j^2]
        float T5 = __shfl_xor_sync(0xffffffffu, T1, 2);  // T[rr][j^6]
        float T6 = __shfl_xor_sync(0xffffffffu, T2, 2);  // T[rr][j^3]
        float T7 = __shfl_xor_sync(0xffffffffu, T3, 2);  // T[rr][j^7]
        float r0 = T0 * P0[0], r1 = T0 * P1[0];
        r0 = fmaf(T1, P0[1], r0); r1 = fmaf(T1, P1[1], r1);
        r0 = fmaf(T2, P0[2], r0); r1 = fmaf(T2, P1[2], r1);
        r0 = fmaf(T3, P0[3], r0); r1 = fmaf(T3, P1[3], r1);
        r0 = fmaf(T4, P0[4], r0); r1 = fmaf(T4, P1[4], r1);
        r0 = fmaf(T5, P0[5], r0); r1 = fmaf(T5, P1[5], r1);
        r0 = fmaf(T6, P0[6], r0); r1 = fmaf(T6, P1[6], r1);
        r0 = fmaf(T7, P0[7], r0); r1 = fmaf(T7, P1[7], r1);
        o0 = r0; o1 = r1;
    };

    // Chroma block (cross-warp consumers -> smem).
    {
        float c0, c1;
        idct_sh(cf0 * dqc0, cf1 * dqc1, c0, c1);
        float* sC  = (w < 4) ? sCb[s] : sCr[s];
        float  off = 128.0f + ((w < 4) ? sShift[1] : sShift[2]);
        float2 cv2 = make_float2(c0 + off, c1 + off);
        *reinterpret_cast<float2*>(&sC[(rr << 3) + v0]) = cv2;
    }

    float yv[4];
    idct_sh(yf00 * dqy0, yf01 * dqy1, yv[0], yv[1]);   // Y block row 0
    idct_sh(yf10 * dqy0, yf11 * dqy1, yv[2], yv[3]);   // Y block row 1

    __syncthreads();   // chroma visible to all warps                    [BAR 2]

    const float m0 = sMat[0], m1 = sMat[1], m2 = sMat[2];
    const float m3 = sMat[3], m4 = sMat[4], m5 = sMat[5];
    const float m6 = sMat[6], m7 = sMat[7], m8 = sMat[8];
    const float c128 = 128.0f + sShift[0];
    const float inv255 = 1.0f / 255.0f;

    const int g2  = w >> 1;                    // 16x16 subtile of this warp
    const int pcl = ((w & 1) << 3) + v0;       // col within subtile (even)
    const long long colBase = w0 + (w << 3) + v0;
    float2* out2 = reinterpret_cast<float2*>(out);

    #pragma unroll
    for (int q = 0; q < 2; ++q) {
        int pr = (q << 3) + rr;                // row within 16
        int ci = ((pr >> 1) << 3) + (pcl >> 1);
        float Cb_ = sCb[g2][ci];
        float Cr_ = sCr[g2][ci];
        float Y0 = yv[(q << 1)]     + c128;
        float Y1 = yv[(q << 1) + 1] + c128;
        float R0 = fmaf(Cr_, m6, fmaf(Cb_, m3, Y0 * m0));
        float G0 = fmaf(Cr_, m7, fmaf(Cb_, m4, Y0 * m1));
        float B0v= fmaf(Cr_, m8, fmaf(Cb_, m5, Y0 * m2));
        float R1 = fmaf(Cr_, m6, fmaf(Cb_, m3, Y1 * m0));
        float G1 = fmaf(Cr_, m7, fmaf(Cb_, m4, Y1 * m1));
        float B1v= fmaf(Cr_, m8, fmaf(Cb_, m5, Y1 * m2));
        R0 = fminf(fmaxf(R0, 0.f), 255.f) * inv255;
        G0 = fminf(fmaxf(G0, 0.f), 255.f) * inv255;
        B0v= fminf(fmaxf(B0v,0.f), 255.f) * inv255;
        R1 = fminf(fmaxf(R1, 0.f), 255.f) * inv255;
        G1 = fminf(fmaxf(G1, 0.f), 255.f) * inv255;
        B1v= fminf(fmaxf(B1v,0.f), 255.f) * inv255;
        long long rowOff = (long long)(h0 + pr) * W + colBase;
        long long chStride = (long long)H * W;
        long long base = ((long long)b * 3) * chStride + rowOff;
        out2[(base)                 >> 1] = make_float2(R0, R1);
        out2[(base + chStride)      >> 1] = make_float2(G0, G1);
        out2[(base + 2 * chStride)  >> 1] = make_float2(B0v, B1v);
    }
}

extern "C" void kernel_launch(void* const* d_in, const int* in_sizes, int n_in,
                              void* d_out, int out_size) {
    // metadata order: y, cb, cr, y_table, c_table, alpha, dct_tensor,
    //                 shift, matrix, image_height, image_width, factor
    const float* yc   = (const float*)d_in[0];
    const float* cbv  = (const float*)d_in[1];
    const float* crv  = (const float*)d_in[2];
    const float* ytab = (const float*)d_in[3];
    const float* ctab = (const float*)d_in[4];
    const float* alp  = (const float*)d_in[5];
    // d_in[6] dct_tensor unused (basis built analytically with cospif)
    const float* shf  = (const float*)d_in[7];
    const float* mat  = (const float*)d_in[8];
    const int*   Hp   = (const int*)d_in[9];
    const int*   Wp   = (const int*)d_in[10];
    const int*   fac  = (const int*)d_in[11];
    float* out = (float*)d_out;

    int tiles = out_size / (3 * 16 * 64);   // one CTA per 16x64 output tile
    jpeg_decode_kernel<<<tiles, 256>>>(yc, cbv, crv, ytab, ctab, alp,
                                       shf, mat, Hp, Wp, fac, out);
}